// round 1
// baseline (speedup 1.0000x reference)
#include <cuda_runtime.h>
#include <math.h>

#define Bdim 2
#define Ndim 2048
#define Edim 384
#define DPdim 16
#define KSEL 32
#define EPSV 1e-8f
#define BLK 256

// scratch (device globals: no allocation allowed)
__device__ float g_z[Bdim * Ndim * DPdim];
__device__ float g_rz[Bdim * Ndim];
__device__ float g_rp[Ndim];

// Abramowitz-Stegun 7.1.26, max abs err 1.5e-7, branch-free
__device__ __forceinline__ float erf_fast(float x) {
    float ax = fabsf(x);
    float t = __fdividef(1.0f, fmaf(0.3275911f, ax, 1.0f));
    float poly = t * fmaf(t, fmaf(t, fmaf(t, fmaf(t, 1.061405429f, -1.453152027f),
                                          1.421413741f), -0.284496736f), 0.254829592f);
    float r = 1.0f - poly * __expf(-ax * ax);
    return copysignf(r, x);
}

__device__ __forceinline__ float gelu_exact(float x) {
    return 0.5f * x * (1.0f + erf_fast(x * 0.70710678118654752f));
}

// ---------------- kernel 1: rp[n] = ||positions[n]||^2 ----------------
__global__ void prep_kernel(const float* __restrict__ positions) {
    int n = blockIdx.x * blockDim.x + threadIdx.x;
    if (n < Ndim) {
        float x = positions[3 * n + 0];
        float y = positions[3 * n + 1];
        float z = positions[3 * n + 2];
        g_rp[n] = x * x + y * y + z * z;
    }
}

// ---------------- kernel 2: z = gelu(f@Wi1+bi1)@Wi2+bi2, rz = ||z||^2 ----
__global__ __launch_bounds__(256) void z_kernel(
    const float* __restrict__ feat, const float* __restrict__ Wi1,
    const float* __restrict__ bi1, const float* __restrict__ Wi2,
    const float* __restrict__ bi2)
{
    int gwarp = (blockIdx.x * blockDim.x + threadIdx.x) >> 5;
    int lane = threadIdx.x & 31;
    if (gwarp >= Bdim * Ndim) return;

    const float* x = feat + (size_t)gwarp * Edim;
    float acc = 0.0f;
    for (int e0 = 0; e0 < Edim; e0 += 32) {
        float xv = x[e0 + lane];
#pragma unroll
        for (int i = 0; i < 32; i++) {
            float xb = __shfl_sync(0xffffffffu, xv, i);
            acc = fmaf(xb, Wi1[(e0 + i) * 32 + lane], acc);
        }
    }
    float hg = gelu_exact(acc + bi1[lane]);

    float wv[DPdim];
#pragma unroll
    for (int d = 0; d < DPdim; d++) wv[d] = Wi2[lane * DPdim + d];

    float zv = 0.0f;
#pragma unroll
    for (int d = 0; d < DPdim; d++) {
        float p = hg * wv[d];
#pragma unroll
        for (int off = 16; off > 0; off >>= 1)
            p += __shfl_xor_sync(0xffffffffu, p, off);
        if (lane == d) zv = p + bi2[d];
    }
    if (lane < DPdim) g_z[gwarp * DPdim + lane] = zv;

    float q = (lane < DPdim) ? zv * zv : 0.0f;
#pragma unroll
    for (int off = 16; off > 0; off >>= 1)
        q += __shfl_xor_sync(0xffffffffu, q, off);
    if (lane == 0) g_rz[gwarp] = q;
}

// ---------------- kernel 3: fused priors + top-k + normalize ----------------
__global__ __launch_bounds__(BLK) void prior_kernel(
    const float* __restrict__ positions,
    const float* __restrict__ Wb1, const float* __restrict__ bb1,
    const float* __restrict__ Wb2, const float* __restrict__ bb2,
    const float* __restrict__ p_sig, const float* __restrict__ p_tau,
    const float* __restrict__ p_alp, const float* __restrict__ prior_logits,
    float* __restrict__ out)
{
    __shared__ float sRow[Ndim];
    __shared__ float4 sWb1v[DPdim * DPdim / 4];
    __shared__ float sWb2[DPdim];
    __shared__ float sBb1[DPdim];
    __shared__ float sZi[DPdim];
    __shared__ float sScal[10]; // inv2sig, inv2tau, alpha, w0..w3, bb2, rpi, rzi
    __shared__ float sPi[3];
    __shared__ int sCnts[32];
    __shared__ int sWeq[8];
    __shared__ float sWsum[8];

    const int tid = threadIdx.x;
    const int lane = tid & 31;
    const int warp = tid >> 5;
    const int row = blockIdx.x;          // b*Ndim + i
    const int b = row >> 11;
    const int i = row & (Ndim - 1);

    if (tid < 64) sWb1v[tid] = ((const float4*)Wb1)[tid];
    if (tid < DPdim) {
        sWb2[tid] = Wb2[tid];
        sBb1[tid] = bb1[tid];
        sZi[tid] = g_z[(size_t)row * DPdim + tid];
    }
    if (tid < 32) sCnts[tid] = 0;
    if (tid == 0) {
        float sg = log1pf(__expf(p_sig[0]));
        float ta = log1pf(__expf(p_tau[0]));
        float al = log1pf(__expf(p_alp[0]));
        sScal[0] = __fdividef(1.0f, 2.0f * sg * sg + EPSV);
        sScal[1] = __fdividef(1.0f, 2.0f * ta * ta + EPSV);
        sScal[2] = al;
        float l0 = prior_logits[0], l1 = prior_logits[1];
        float l2 = prior_logits[2], l3 = prior_logits[3];
        float m = fmaxf(fmaxf(l0, l1), fmaxf(l2, l3));
        float e0 = __expf(l0 - m), e1 = __expf(l1 - m);
        float e2 = __expf(l2 - m), e3 = __expf(l3 - m);
        float inv = __fdividef(1.0f, e0 + e1 + e2 + e3);
        sScal[3] = e0 * inv; sScal[4] = e1 * inv;
        sScal[5] = e2 * inv; sScal[6] = e3 * inv;
        sScal[7] = bb2[0];
        sScal[8] = g_rp[i];
        sScal[9] = g_rz[row];
        sPi[0] = positions[3 * i + 0];
        sPi[1] = positions[3 * i + 1];
        sPi[2] = positions[3 * i + 2];
    }
    __syncthreads();

    const float inv2sig = sScal[0], inv2tau = sScal[1], alpha = sScal[2];
    const float w0 = sScal[3], w1 = sScal[4], w2 = sScal[5], w3 = sScal[6];
    const float bb2v = sScal[7], rpi = sScal[8], rzi = sScal[9];
    const float pix = sPi[0], piy = sPi[1], piz = sPi[2];

    float zi[DPdim];
#pragma unroll
    for (int d = 0; d < DPdim; d++) zi[d] = sZi[d];

    const float4* zg = (const float4*)(g_z + (size_t)b * Ndim * DPdim);
    const float* rzb = g_rz + (size_t)b * Ndim;

    // ---- main pairwise loop: 2 columns per thread per iteration ----
    for (int base = 0; base < Ndim; base += 2 * BLK) {
        int j0 = base + tid, j1 = j0 + BLK;

        float zj0[DPdim], zj1[DPdim];
        {
            float4* v0 = (float4*)zj0;
            float4* v1 = (float4*)zj1;
#pragma unroll
            for (int q = 0; q < 4; q++) { v0[q] = zg[j0 * 4 + q]; v1[q] = zg[j1 * 4 + q]; }
        }
        float rz0 = rzb[j0], rz1 = rzb[j1];
        float pj0x = positions[3 * j0 + 0], pj0y = positions[3 * j0 + 1], pj0z = positions[3 * j0 + 2];
        float pj1x = positions[3 * j1 + 0], pj1y = positions[3 * j1 + 1], pj1z = positions[3 * j1 + 2];
        float rp0 = g_rp[j0], rp1 = g_rp[j1];

        float h0[DPdim], h1[DPdim];
#pragma unroll
        for (int o = 0; o < DPdim; o++) { h0[o] = sBb1[o]; h1[o] = sBb1[o]; }

        float dz0 = 0.0f, dz1 = 0.0f;
#pragma unroll
        for (int d = 0; d < DPdim; d++) {
            float zid = zi[d];
            dz0 = fmaf(zid, zj0[d], dz0);
            dz1 = fmaf(zid, zj1[d], dz1);
            float e0 = fabsf(zid - zj0[d]);
            float e1 = fabsf(zid - zj1[d]);
#pragma unroll
            for (int o4 = 0; o4 < 4; o4++) {
                float4 w = sWb1v[d * 4 + o4];
                h0[o4 * 4 + 0] = fmaf(e0, w.x, h0[o4 * 4 + 0]);
                h0[o4 * 4 + 1] = fmaf(e0, w.y, h0[o4 * 4 + 1]);
                h0[o4 * 4 + 2] = fmaf(e0, w.z, h0[o4 * 4 + 2]);
                h0[o4 * 4 + 3] = fmaf(e0, w.w, h0[o4 * 4 + 3]);
                h1[o4 * 4 + 0] = fmaf(e1, w.x, h1[o4 * 4 + 0]);
                h1[o4 * 4 + 1] = fmaf(e1, w.y, h1[o4 * 4 + 1]);
                h1[o4 * 4 + 2] = fmaf(e1, w.z, h1[o4 * 4 + 2]);
                h1[o4 * 4 + 3] = fmaf(e1, w.w, h1[o4 * 4 + 3]);
            }
        }

        float s0 = bb2v, s1 = bb2v;
#pragma unroll
        for (int o = 0; o < DPdim; o++) {
            float wb = sWb2[o];
            s0 = fmaf(gelu_exact(h0[o]), wb, s0);
            s1 = fmaf(gelu_exact(h1[o]), wb, s1);
        }
        float abnd0 = __fdividef(1.0f, 1.0f + __expf(alpha * s0));
        float abnd1 = __fdividef(1.0f, 1.0f + __expf(alpha * s1));

        float d2z0 = fmaxf(rzi + rz0 - 2.0f * dz0, 0.0f);
        float d2z1 = fmaxf(rzi + rz1 - 2.0f * dz1, 0.0f);
        float aint0 = __expf(-d2z0 * inv2tau);
        float aint1 = __expf(-d2z1 * inv2tau);

        float dp0 = pix * pj0x + piy * pj0y + piz * pj0z;
        float dp1 = pix * pj1x + piy * pj1y + piz * pj1z;
        float d2p0 = fmaxf(rpi + rp0 - 2.0f * dp0, 0.0f);
        float d2p1 = fmaxf(rpi + rp1 - 2.0f * dp1, 0.0f);
        float asp0 = __expf(-d2p0 * inv2sig);
        float asp1 = __expf(-d2p1 * inv2sig);

        float A0 = w0 * asp0 + w1 * aint0 + w2 * abnd0 + w3;
        float A1 = w0 * asp1 + w1 * aint1 + w2 * abnd1 + w3;
        A0 = fminf(fmaxf(A0, 0.0f), 1.0f);
        A1 = fminf(fmaxf(A1, 0.0f), 1.0f);
        if (j0 == i) A0 = 0.0f;
        if (j1 == i) A1 = 0.0f;
        sRow[j0] = A0;
        sRow[j1] = A1;
    }
    __syncthreads();

    // ---- top-k (k=32): radix bit-descent on float bits (all values >= 0) ----
    unsigned vb[8];
#pragma unroll
    for (int r = 0; r < 8; r++) vb[r] = __float_as_uint(sRow[tid * 8 + r]);

    unsigned T = 0u;
    for (int bit = 30; bit >= 0; bit--) {
        unsigned cand = T | (1u << bit);
        int c = 0;
#pragma unroll
        for (int r = 0; r < 8; r++) c += (vb[r] >= cand);
        c = __reduce_add_sync(0xffffffffu, c);
        if (lane == 0) atomicAdd(&sCnts[bit], c);
        __syncthreads();
        if (sCnts[bit] >= KSEL) T = cand;
    }

    // strict-greater count -> how many ties at T we must keep (index order)
    {
        int c = 0;
#pragma unroll
        for (int r = 0; r < 8; r++) c += (vb[r] > T);
        c = __reduce_add_sync(0xffffffffu, c);
        if (lane == 0) atomicAdd(&sCnts[31], c);
    }
    __syncthreads();
    const int need = KSEL - sCnts[31];

    // exclusive scan of per-thread equal-to-T counts (global index order)
    int eqc = 0;
#pragma unroll
    for (int r = 0; r < 8; r++) eqc += (vb[r] == T);
    int incl = eqc;
#pragma unroll
    for (int off = 1; off < 32; off <<= 1) {
        int t = __shfl_up_sync(0xffffffffu, incl, off);
        if (lane >= off) incl += t;
    }
    if (lane == 31) sWeq[warp] = incl;
    __syncthreads();
    int ebase = incl - eqc;
    for (int w = 0; w < warp; w++) ebase += sWeq[w];

    // kept-sum (deterministic block reduce)
    float ksum = 0.0f;
    {
        int rk = ebase;
#pragma unroll
        for (int r = 0; r < 8; r++) {
            unsigned u = vb[r];
            float v = __uint_as_float(u);
            if (u > T) ksum += v;
            else if (u == T) { if (rk < need) ksum += v; rk++; }
        }
    }
#pragma unroll
    for (int off = 16; off > 0; off >>= 1)
        ksum += __shfl_xor_sync(0xffffffffu, ksum, off);
    if (lane == 0) sWsum[warp] = ksum;
    __syncthreads();
    float tot = 0.0f;
#pragma unroll
    for (int w = 0; w < 8; w++) tot += sWsum[w];
    const float inv = __fdividef(1.0f, fmaxf(tot, EPSV));

    // write normalized sparse row (coalesced float4 stores)
    float ov[8];
    {
        int rk = ebase;
#pragma unroll
        for (int r = 0; r < 8; r++) {
            unsigned u = vb[r];
            float v = __uint_as_float(u);
            bool keep = (u > T);
            if (u == T) { keep = (rk < need); rk++; }
            ov[r] = keep ? v * inv : 0.0f;
        }
    }
    float4* orow4 = (float4*)(out + (size_t)row * Ndim);
    orow4[tid * 2 + 0] = make_float4(ov[0], ov[1], ov[2], ov[3]);
    orow4[tid * 2 + 1] = make_float4(ov[4], ov[5], ov[6], ov[7]);
}

extern "C" void kernel_launch(void* const* d_in, const int* in_sizes, int n_in,
                              void* d_out, int out_size) {
    const float* features     = (const float*)d_in[0];
    const float* positions    = (const float*)d_in[1];
    const float* Wi1          = (const float*)d_in[2];
    const float* bi1          = (const float*)d_in[3];
    const float* Wi2          = (const float*)d_in[4];
    const float* bi2          = (const float*)d_in[5];
    const float* Wb1          = (const float*)d_in[6];
    const float* bb1          = (const float*)d_in[7];
    const float* Wb2          = (const float*)d_in[8];
    const float* bb2          = (const float*)d_in[9];
    const float* log_sigma    = (const float*)d_in[10];
    const float* log_tau      = (const float*)d_in[11];
    const float* log_alpha    = (const float*)d_in[12];
    // d_in[13] = log_gamma (unused: EMA buffer empty -> stability == 1)
    const float* prior_logits = (const float*)d_in[14];
    float* out = (float*)d_out;

    prep_kernel<<<(Ndim + 255) / 256, 256>>>(positions);
    z_kernel<<<(Bdim * Ndim * 32) / 256, 256>>>(features, Wi1, bi1, Wi2, bi2);
    prior_kernel<<<Bdim * Ndim, BLK>>>(positions, Wb1, bb1, Wb2, bb2,
                                       log_sigma, log_tau, log_alpha,
                                       prior_logits, out);
}

// round 2
// speedup vs baseline: 2.1361x; 2.1361x over previous
#include <cuda_runtime.h>
#include <math.h>

#define Bdim 2
#define Ndim 2048
#define Edim 384
#define DPdim 16
#define KSEL 32
#define EPSV 1e-8f
#define TN 64
#define NT (Ndim / TN)            // 32
#define NTRI (NT * (NT + 1) / 2)  // 528

// scratch (device globals: no allocation allowed)
__device__ float g_z[Bdim * Ndim * DPdim];
__device__ float g_rz[Bdim * Ndim];
__device__ float g_rp[Ndim];
__device__ float g_A[(size_t)Bdim * Ndim * Ndim];  // 33.5 MB dense prior matrix

// Abramowitz-Stegun 7.1.26, max abs err 1.5e-7, branch-free
__device__ __forceinline__ float erf_fast(float x) {
    float ax = fabsf(x);
    float t = __fdividef(1.0f, fmaf(0.3275911f, ax, 1.0f));
    float poly = t * fmaf(t, fmaf(t, fmaf(t, fmaf(t, 1.061405429f, -1.453152027f),
                                          1.421413741f), -0.284496736f), 0.254829592f);
    float r = 1.0f - poly * __expf(-ax * ax);
    return copysignf(r, x);
}

__device__ __forceinline__ float gelu_exact(float x) {
    return 0.5f * x * (1.0f + erf_fast(x * 0.70710678118654752f));
}

// ---------------- kernel 1: rp[n] = ||positions[n]||^2 ----------------
__global__ void prep_kernel(const float* __restrict__ positions) {
    int n = blockIdx.x * blockDim.x + threadIdx.x;
    if (n < Ndim) {
        float x = positions[3 * n + 0];
        float y = positions[3 * n + 1];
        float z = positions[3 * n + 2];
        g_rp[n] = x * x + y * y + z * z;
    }
}

// ---------------- kernel 2: z = gelu(f@Wi1+bi1)@Wi2+bi2, rz = ||z||^2 ----
__global__ __launch_bounds__(256) void z_kernel(
    const float* __restrict__ feat, const float* __restrict__ Wi1,
    const float* __restrict__ bi1, const float* __restrict__ Wi2,
    const float* __restrict__ bi2)
{
    int gwarp = (blockIdx.x * blockDim.x + threadIdx.x) >> 5;
    int lane = threadIdx.x & 31;
    if (gwarp >= Bdim * Ndim) return;

    const float* x = feat + (size_t)gwarp * Edim;
    float acc = 0.0f;
    for (int e0 = 0; e0 < Edim; e0 += 32) {
        float xv = x[e0 + lane];
#pragma unroll
        for (int i = 0; i < 32; i++) {
            float xb = __shfl_sync(0xffffffffu, xv, i);
            acc = fmaf(xb, Wi1[(e0 + i) * 32 + lane], acc);
        }
    }
    float hg = gelu_exact(acc + bi1[lane]);

    float wv[DPdim];
#pragma unroll
    for (int d = 0; d < DPdim; d++) wv[d] = Wi2[lane * DPdim + d];

    float zv = 0.0f;
#pragma unroll
    for (int d = 0; d < DPdim; d++) {
        float p = hg * wv[d];
#pragma unroll
        for (int off = 16; off > 0; off >>= 1)
            p += __shfl_xor_sync(0xffffffffu, p, off);
        if (lane == d) zv = p + bi2[d];
    }
    if (lane < DPdim) g_z[gwarp * DPdim + lane] = zv;

    float q = (lane < DPdim) ? zv * zv : 0.0f;
#pragma unroll
    for (int off = 16; off > 0; off >>= 1)
        q += __shfl_xor_sync(0xffffffffu, q, off);
    if (lane == 0) g_rz[gwarp] = q;
}

// ---------------- kernel 3: triangular tile pair-compute -> g_A -------------
// grid = Bdim * NTRI blocks; each block computes a 64x64 tile (ti <= tj) and
// writes both orientations (symmetric by construction).
__global__ __launch_bounds__(256) void tile_kernel(
    const float* __restrict__ positions,
    const float* __restrict__ Wb1, const float* __restrict__ bb1,
    const float* __restrict__ Wb2, const float* __restrict__ bb2,
    const float* __restrict__ p_sig, const float* __restrict__ p_tau,
    const float* __restrict__ p_alp, const float* __restrict__ prior_logits)
{
    __shared__ float sZi[TN * DPdim];
    __shared__ float sRzI[TN], sRpI[TN];
    __shared__ float sPiX[TN], sPiY[TN], sPiZ[TN];
    __shared__ float4 sWb1v[DPdim * DPdim / 4];
    __shared__ float sWb2[DPdim];
    __shared__ float sBb1[DPdim];
    __shared__ float sScal[8]; // inv2sig, inv2tau, alpha, w0..w3, bb2
    __shared__ float sTile[TN][TN + 1];

    const int tid = threadIdx.x;
    const int jl = tid & 63;
    const int ig = tid >> 6;   // 0..3: i-band of 16 rows

    // decode (b, ti, tj)
    int blk = blockIdx.x;
    const int b = blk / NTRI;
    int tri = blk - b * NTRI;
    int ti = 0;
    while (tri >= NT - ti) { tri -= NT - ti; ti++; }
    const int tj = ti + tri;
    const int I = ti * TN, J = tj * TN;

    // cooperative loads
    if (tid < 64) sWb1v[tid] = ((const float4*)Wb1)[tid];
    if (tid >= 64 && tid < 80) {
        sWb2[tid - 64] = Wb2[tid - 64];
        sBb1[tid - 64] = bb1[tid - 64];
    }
    {   // sZi: 64 rows x 16 floats = 256 float4
        const float4* zgi = (const float4*)(g_z + ((size_t)b * Ndim + I) * DPdim);
        ((float4*)sZi)[tid] = zgi[tid];
    }
    if (tid < 64) {
        int gi = I + tid;
        sRzI[tid] = g_rz[(size_t)b * Ndim + gi];
        sRpI[tid] = g_rp[gi];
        sPiX[tid] = positions[3 * gi + 0];
        sPiY[tid] = positions[3 * gi + 1];
        sPiZ[tid] = positions[3 * gi + 2];
    }
    if (tid == 128) {
        float sg = log1pf(__expf(p_sig[0]));
        float ta = log1pf(__expf(p_tau[0]));
        float al = log1pf(__expf(p_alp[0]));
        sScal[0] = __fdividef(1.0f, 2.0f * sg * sg + EPSV);
        sScal[1] = __fdividef(1.0f, 2.0f * ta * ta + EPSV);
        sScal[2] = al;
        float l0 = prior_logits[0], l1 = prior_logits[1];
        float l2 = prior_logits[2], l3 = prior_logits[3];
        float m = fmaxf(fmaxf(l0, l1), fmaxf(l2, l3));
        float e0 = __expf(l0 - m), e1 = __expf(l1 - m);
        float e2 = __expf(l2 - m), e3 = __expf(l3 - m);
        float inv = __fdividef(1.0f, e0 + e1 + e2 + e3);
        sScal[3] = e0 * inv; sScal[4] = e1 * inv;
        sScal[5] = e2 * inv; sScal[6] = e3 * inv;
        sScal[7] = bb2[0];
    }

    // per-thread j-side data (fixed column)
    const int gj = J + jl;
    float zj[DPdim];
    {
        const float4* zgj = (const float4*)(g_z + ((size_t)b * Ndim + gj) * DPdim);
        float4* v = (float4*)zj;
#pragma unroll
        for (int q = 0; q < 4; q++) v[q] = zgj[q];
    }
    const float rzj = g_rz[(size_t)b * Ndim + gj];
    const float rpj = g_rp[gj];
    const float pjx = positions[3 * gj + 0];
    const float pjy = positions[3 * gj + 1];
    const float pjz = positions[3 * gj + 2];

    __syncthreads();

    const float inv2sig = sScal[0], inv2tau = sScal[1], alpha = sScal[2];
    const float w0 = sScal[3], w1 = sScal[4], w2 = sScal[5], w3 = sScal[6];
    const float bb2v = sScal[7];

    // 8 iterations x 2 i-rows per thread
#pragma unroll 1
    for (int it = 0; it < 8; it++) {
        const int i0 = ig * 16 + it * 2;
        const int i1 = i0 + 1;

        float h0[DPdim], h1[DPdim];
#pragma unroll
        for (int o = 0; o < DPdim; o++) { h0[o] = sBb1[o]; h1[o] = sBb1[o]; }

        float dz0 = 0.0f, dz1 = 0.0f;
#pragma unroll
        for (int d = 0; d < DPdim; d++) {
            float zi0 = sZi[i0 * DPdim + d];
            float zi1 = sZi[i1 * DPdim + d];
            float zjd = zj[d];
            dz0 = fmaf(zi0, zjd, dz0);
            dz1 = fmaf(zi1, zjd, dz1);
            float e0 = fabsf(zi0 - zjd);
            float e1 = fabsf(zi1 - zjd);
#pragma unroll
            for (int o4 = 0; o4 < 4; o4++) {
                float4 w = sWb1v[d * 4 + o4];
                h0[o4 * 4 + 0] = fmaf(e0, w.x, h0[o4 * 4 + 0]);
                h0[o4 * 4 + 1] = fmaf(e0, w.y, h0[o4 * 4 + 1]);
                h0[o4 * 4 + 2] = fmaf(e0, w.z, h0[o4 * 4 + 2]);
                h0[o4 * 4 + 3] = fmaf(e0, w.w, h0[o4 * 4 + 3]);
                h1[o4 * 4 + 0] = fmaf(e1, w.x, h1[o4 * 4 + 0]);
                h1[o4 * 4 + 1] = fmaf(e1, w.y, h1[o4 * 4 + 1]);
                h1[o4 * 4 + 2] = fmaf(e1, w.z, h1[o4 * 4 + 2]);
                h1[o4 * 4 + 3] = fmaf(e1, w.w, h1[o4 * 4 + 3]);
            }
        }

        float s0 = bb2v, s1 = bb2v;
#pragma unroll
        for (int o = 0; o < DPdim; o++) {
            float wb = sWb2[o];
            s0 = fmaf(gelu_exact(h0[o]), wb, s0);
            s1 = fmaf(gelu_exact(h1[o]), wb, s1);
        }
        float abnd0 = __fdividef(1.0f, 1.0f + __expf(alpha * s0));
        float abnd1 = __fdividef(1.0f, 1.0f + __expf(alpha * s1));

        float d2z0 = fmaxf(sRzI[i0] + rzj - 2.0f * dz0, 0.0f);
        float d2z1 = fmaxf(sRzI[i1] + rzj - 2.0f * dz1, 0.0f);
        float aint0 = __expf(-d2z0 * inv2tau);
        float aint1 = __expf(-d2z1 * inv2tau);

        float dp0 = sPiX[i0] * pjx + sPiY[i0] * pjy + sPiZ[i0] * pjz;
        float dp1 = sPiX[i1] * pjx + sPiY[i1] * pjy + sPiZ[i1] * pjz;
        float d2p0 = fmaxf(sRpI[i0] + rpj - 2.0f * dp0, 0.0f);
        float d2p1 = fmaxf(sRpI[i1] + rpj - 2.0f * dp1, 0.0f);
        float asp0 = __expf(-d2p0 * inv2sig);
        float asp1 = __expf(-d2p1 * inv2sig);

        float A0 = w0 * asp0 + w1 * aint0 + w2 * abnd0 + w3;
        float A1 = w0 * asp1 + w1 * aint1 + w2 * abnd1 + w3;
        A0 = fminf(fmaxf(A0, 0.0f), 1.0f);
        A1 = fminf(fmaxf(A1, 0.0f), 1.0f);
        if (I + i0 == gj) A0 = 0.0f;
        if (I + i1 == gj) A1 = 0.0f;
        sTile[i0][jl] = A0;
        sTile[i1][jl] = A1;
    }
    __syncthreads();

    // write normal orientation: rows I+r, cols J..J+63
    {
        float* baseN = g_A + ((size_t)b * Ndim + I) * Ndim + J;
#pragma unroll
        for (int q = 0; q < 4; q++) {
            int idx = q * 256 + tid;          // float4 slot 0..1023
            int r = idx >> 4;
            int c = (idx & 15) * 4;
            float4 v = make_float4(sTile[r][c], sTile[r][c + 1],
                                   sTile[r][c + 2], sTile[r][c + 3]);
            *(float4*)(baseN + (size_t)r * Ndim + c) = v;
        }
    }
    // transposed orientation: rows J+r, cols I..I+63
    if (ti != tj) {
        float* baseT = g_A + ((size_t)b * Ndim + J) * Ndim + I;
#pragma unroll
        for (int q = 0; q < 4; q++) {
            int idx = q * 256 + tid;
            int r = idx >> 4;
            int c = (idx & 15) * 4;
            float4 v = make_float4(sTile[c][r], sTile[c + 1][r],
                                   sTile[c + 2][r], sTile[c + 3][r]);
            *(float4*)(baseT + (size_t)r * Ndim + c) = v;
        }
    }
}

// ---------------- kernel 4: per-row top-k + normalize -----------------------
__global__ __launch_bounds__(256) void topk_kernel(float* __restrict__ out) {
    __shared__ int sCnts[32];
    __shared__ int sWeq[8];
    __shared__ float sWsum[8];

    const int tid = threadIdx.x;
    const int lane = tid & 31;
    const int warp = tid >> 5;
    const int row = blockIdx.x;

    if (tid < 32) sCnts[tid] = 0;

    unsigned vb[8];
    {
        const float4* rowp = (const float4*)(g_A + (size_t)row * Ndim);
        float4 a = rowp[tid * 2 + 0];
        float4 c = rowp[tid * 2 + 1];
        vb[0] = __float_as_uint(a.x); vb[1] = __float_as_uint(a.y);
        vb[2] = __float_as_uint(a.z); vb[3] = __float_as_uint(a.w);
        vb[4] = __float_as_uint(c.x); vb[5] = __float_as_uint(c.y);
        vb[6] = __float_as_uint(c.z); vb[7] = __float_as_uint(c.w);
    }
    __syncthreads();

    // radix bit-descent (values in [0,1] -> bit 30 never set)
    unsigned T = 0u;
    for (int bit = 29; bit >= 0; bit--) {
        unsigned cand = T | (1u << bit);
        int c = 0;
#pragma unroll
        for (int r = 0; r < 8; r++) c += (vb[r] >= cand);
        c = __reduce_add_sync(0xffffffffu, c);
        if (lane == 0) atomicAdd(&sCnts[bit], c);
        __syncthreads();
        if (sCnts[bit] >= KSEL) T = cand;
    }

    {
        int c = 0;
#pragma unroll
        for (int r = 0; r < 8; r++) c += (vb[r] > T);
        c = __reduce_add_sync(0xffffffffu, c);
        if (lane == 0) atomicAdd(&sCnts[31], c);
    }
    __syncthreads();
    const int need = KSEL - sCnts[31];

    int eqc = 0;
#pragma unroll
    for (int r = 0; r < 8; r++) eqc += (vb[r] == T);
    int incl = eqc;
#pragma unroll
    for (int off = 1; off < 32; off <<= 1) {
        int t = __shfl_up_sync(0xffffffffu, incl, off);
        if (lane >= off) incl += t;
    }
    if (lane == 31) sWeq[warp] = incl;
    __syncthreads();
    int ebase = incl - eqc;
    for (int w = 0; w < warp; w++) ebase += sWeq[w];

    float ksum = 0.0f;
    {
        int rk = ebase;
#pragma unroll
        for (int r = 0; r < 8; r++) {
            unsigned u = vb[r];
            float v = __uint_as_float(u);
            if (u > T) ksum += v;
            else if (u == T) { if (rk < need) ksum += v; rk++; }
        }
    }
#pragma unroll
    for (int off = 16; off > 0; off >>= 1)
        ksum += __shfl_xor_sync(0xffffffffu, ksum, off);
    if (lane == 0) sWsum[warp] = ksum;
    __syncthreads();
    float tot = 0.0f;
#pragma unroll
    for (int w = 0; w < 8; w++) tot += sWsum[w];
    const float inv = __fdividef(1.0f, fmaxf(tot, EPSV));

    float ov[8];
    {
        int rk = ebase;
#pragma unroll
        for (int r = 0; r < 8; r++) {
            unsigned u = vb[r];
            float v = __uint_as_float(u);
            bool keep = (u > T);
            if (u == T) { keep = (rk < need); rk++; }
            ov[r] = keep ? v * inv : 0.0f;
        }
    }
    float4* orow4 = (float4*)(out + (size_t)row * Ndim);
    orow4[tid * 2 + 0] = make_float4(ov[0], ov[1], ov[2], ov[3]);
    orow4[tid * 2 + 1] = make_float4(ov[4], ov[5], ov[6], ov[7]);
}

extern "C" void kernel_launch(void* const* d_in, const int* in_sizes, int n_in,
                              void* d_out, int out_size) {
    const float* features     = (const float*)d_in[0];
    const float* positions    = (const float*)d_in[1];
    const float* Wi1          = (const float*)d_in[2];
    const float* bi1          = (const float*)d_in[3];
    const float* Wi2          = (const float*)d_in[4];
    const float* bi2          = (const float*)d_in[5];
    const float* Wb1          = (const float*)d_in[6];
    const float* bb1          = (const float*)d_in[7];
    const float* Wb2          = (const float*)d_in[8];
    const float* bb2          = (const float*)d_in[9];
    const float* log_sigma    = (const float*)d_in[10];
    const float* log_tau      = (const float*)d_in[11];
    const float* log_alpha    = (const float*)d_in[12];
    // d_in[13] = log_gamma (unused: EMA buffer empty -> stability == 1)
    const float* prior_logits = (const float*)d_in[14];
    float* out = (float*)d_out;

    prep_kernel<<<(Ndim + 255) / 256, 256>>>(positions);
    z_kernel<<<(Bdim * Ndim * 32) / 256, 256>>>(features, Wi1, bi1, Wi2, bi2);
    tile_kernel<<<Bdim * NTRI, 256>>>(positions, Wb1, bb1, Wb2, bb2,
                                      log_sigma, log_tau, log_alpha, prior_logits);
    topk_kernel<<<Bdim * Ndim, 256>>>(out);
}

// round 3
// speedup vs baseline: 2.2998x; 1.0766x over previous
#include <cuda_runtime.h>
#include <math.h>

#define Bdim 2
#define Ndim 2048
#define Edim 384
#define DPdim 16
#define KSEL 32
#define EPSV 1e-8f
#define TN 64
#define NT (Ndim / TN)            // 32
#define NTRI (NT * (NT + 1) / 2)  // 528

// scratch (device globals: no allocation allowed)
__device__ float g_z[Bdim * Ndim * DPdim];
__device__ float g_rz[Bdim * Ndim];
__device__ float g_rp[Ndim];
__device__ float g_A[(size_t)Bdim * Ndim * Ndim];  // 33.5 MB dense prior matrix

// Abramowitz-Stegun 7.1.26, max abs err 1.5e-7, branch-free
__device__ __forceinline__ float erf_fast(float x) {
    float ax = fabsf(x);
    float t = __fdividef(1.0f, fmaf(0.3275911f, ax, 1.0f));
    float poly = t * fmaf(t, fmaf(t, fmaf(t, fmaf(t, 1.061405429f, -1.453152027f),
                                          1.421413741f), -0.284496736f), 0.254829592f);
    float r = 1.0f - poly * __expf(-ax * ax);
    return copysignf(r, x);
}

__device__ __forceinline__ float gelu_exact(float x) {
    return 0.5f * x * (1.0f + erf_fast(x * 0.70710678118654752f));
}

// ---------------- kernel 1: rp[n] = ||positions[n]||^2 ----------------
__global__ void prep_kernel(const float* __restrict__ positions) {
    int n = blockIdx.x * blockDim.x + threadIdx.x;
    if (n < Ndim) {
        float x = positions[3 * n + 0];
        float y = positions[3 * n + 1];
        float z = positions[3 * n + 2];
        g_rp[n] = x * x + y * y + z * z;
    }
}

// ---------------- kernel 2: z = gelu(f@Wi1+bi1)@Wi2+bi2, rz = ||z||^2 ----
__global__ __launch_bounds__(256) void z_kernel(
    const float* __restrict__ feat, const float* __restrict__ Wi1,
    const float* __restrict__ bi1, const float* __restrict__ Wi2,
    const float* __restrict__ bi2)
{
    int gwarp = (blockIdx.x * blockDim.x + threadIdx.x) >> 5;
    int lane = threadIdx.x & 31;
    if (gwarp >= Bdim * Ndim) return;

    const float* x = feat + (size_t)gwarp * Edim;
    float acc = 0.0f;
    for (int e0 = 0; e0 < Edim; e0 += 32) {
        float xv = x[e0 + lane];
#pragma unroll
        for (int i = 0; i < 32; i++) {
            float xb = __shfl_sync(0xffffffffu, xv, i);
            acc = fmaf(xb, Wi1[(e0 + i) * 32 + lane], acc);
        }
    }
    float hg = gelu_exact(acc + bi1[lane]);

    float wv[DPdim];
#pragma unroll
    for (int d = 0; d < DPdim; d++) wv[d] = Wi2[lane * DPdim + d];

    float zv = 0.0f;
#pragma unroll
    for (int d = 0; d < DPdim; d++) {
        float p = hg * wv[d];
#pragma unroll
        for (int off = 16; off > 0; off >>= 1)
            p += __shfl_xor_sync(0xffffffffu, p, off);
        if (lane == d) zv = p + bi2[d];
    }
    if (lane < DPdim) g_z[gwarp * DPdim + lane] = zv;

    float q = (lane < DPdim) ? zv * zv : 0.0f;
#pragma unroll
    for (int off = 16; off > 0; off >>= 1)
        q += __shfl_xor_sync(0xffffffffu, q, off);
    if (lane == 0) g_rz[gwarp] = q;
}

// ---------------- kernel 3: triangular tile pair-compute -> g_A -------------
// grid = Bdim * NTRI blocks; each block computes a 64x64 tile (ti <= tj) and
// writes both orientations (symmetric by construction).
// Each thread: fixed column j, 4 i-rows per iteration (weight-LDS amortized 4x).
__global__ __launch_bounds__(256) void tile_kernel(
    const float* __restrict__ positions,
    const float* __restrict__ Wb1, const float* __restrict__ bb1,
    const float* __restrict__ Wb2, const float* __restrict__ bb2,
    const float* __restrict__ p_sig, const float* __restrict__ p_tau,
    const float* __restrict__ p_alp, const float* __restrict__ prior_logits)
{
    __shared__ float sZi[TN * DPdim];
    __shared__ float sRzI[TN], sRpI[TN];
    __shared__ float sPiX[TN], sPiY[TN], sPiZ[TN];
    __shared__ float4 sWb1v[DPdim * DPdim / 4];
    __shared__ float sWb2[DPdim];
    __shared__ float sBb1[DPdim];
    __shared__ float sScal[8]; // inv2sig, inv2tau, alpha, w0..w3, bb2
    __shared__ float sTile[TN][TN + 1];

    const int tid = threadIdx.x;
    const int jl = tid & 63;
    const int ig = tid >> 6;   // 0..3: i-band of 16 rows

    // decode (b, ti, tj)
    int blk = blockIdx.x;
    const int b = blk / NTRI;
    int tri = blk - b * NTRI;
    int ti = 0;
    while (tri >= NT - ti) { tri -= NT - ti; ti++; }
    const int tj = ti + tri;
    const int I = ti * TN, J = tj * TN;

    // cooperative loads
    if (tid < 64) sWb1v[tid] = ((const float4*)Wb1)[tid];
    if (tid >= 64 && tid < 80) {
        sWb2[tid - 64] = Wb2[tid - 64];
        sBb1[tid - 64] = bb1[tid - 64];
    }
    {   // sZi: 64 rows x 16 floats = 256 float4
        const float4* zgi = (const float4*)(g_z + ((size_t)b * Ndim + I) * DPdim);
        ((float4*)sZi)[tid] = zgi[tid];
    }
    if (tid < 64) {
        int gi = I + tid;
        sRzI[tid] = g_rz[(size_t)b * Ndim + gi];
        sRpI[tid] = g_rp[gi];
        sPiX[tid] = positions[3 * gi + 0];
        sPiY[tid] = positions[3 * gi + 1];
        sPiZ[tid] = positions[3 * gi + 2];
    }
    if (tid == 128) {
        float sg = log1pf(__expf(p_sig[0]));
        float ta = log1pf(__expf(p_tau[0]));
        float al = log1pf(__expf(p_alp[0]));
        sScal[0] = __fdividef(1.0f, 2.0f * sg * sg + EPSV);
        sScal[1] = __fdividef(1.0f, 2.0f * ta * ta + EPSV);
        sScal[2] = al;
        float l0 = prior_logits[0], l1 = prior_logits[1];
        float l2 = prior_logits[2], l3 = prior_logits[3];
        float m = fmaxf(fmaxf(l0, l1), fmaxf(l2, l3));
        float e0 = __expf(l0 - m), e1 = __expf(l1 - m);
        float e2 = __expf(l2 - m), e3 = __expf(l3 - m);
        float inv = __fdividef(1.0f, e0 + e1 + e2 + e3);
        sScal[3] = e0 * inv; sScal[4] = e1 * inv;
        sScal[5] = e2 * inv; sScal[6] = e3 * inv;
        sScal[7] = bb2[0];
    }

    // per-thread j-side data (fixed column)
    const int gj = J + jl;
    float zj[DPdim];
    {
        const float4* zgj = (const float4*)(g_z + ((size_t)b * Ndim + gj) * DPdim);
        float4* v = (float4*)zj;
#pragma unroll
        for (int q = 0; q < 4; q++) v[q] = zgj[q];
    }
    const float rzj = g_rz[(size_t)b * Ndim + gj];
    const float rpj = g_rp[gj];
    const float pjx = positions[3 * gj + 0];
    const float pjy = positions[3 * gj + 1];
    const float pjz = positions[3 * gj + 2];

    __syncthreads();

    const float inv2sig = sScal[0], inv2tau = sScal[1], alpha = sScal[2];
    const float w0 = sScal[3], w1 = sScal[4], w2 = sScal[5], w3 = sScal[6];
    const float bb2v = sScal[7];

    // 4 iterations x 4 i-rows per thread
#pragma unroll 1
    for (int it = 0; it < 4; it++) {
        const int ib = ig * 16 + it * 4;

        float h[4][DPdim];
#pragma unroll
        for (int r = 0; r < 4; r++)
#pragma unroll
            for (int o = 0; o < DPdim; o++) h[r][o] = sBb1[o];

        float dz[4] = {0.0f, 0.0f, 0.0f, 0.0f};
#pragma unroll
        for (int d = 0; d < DPdim; d++) {
            float zjd = zj[d];
            float e[4];
#pragma unroll
            for (int r = 0; r < 4; r++) {
                float zir = sZi[(ib + r) * DPdim + d];
                dz[r] = fmaf(zir, zjd, dz[r]);
                e[r] = fabsf(zir - zjd);
            }
#pragma unroll
            for (int o4 = 0; o4 < 4; o4++) {
                float4 w = sWb1v[d * 4 + o4];
#pragma unroll
                for (int r = 0; r < 4; r++) {
                    h[r][o4 * 4 + 0] = fmaf(e[r], w.x, h[r][o4 * 4 + 0]);
                    h[r][o4 * 4 + 1] = fmaf(e[r], w.y, h[r][o4 * 4 + 1]);
                    h[r][o4 * 4 + 2] = fmaf(e[r], w.z, h[r][o4 * 4 + 2]);
                    h[r][o4 * 4 + 3] = fmaf(e[r], w.w, h[r][o4 * 4 + 3]);
                }
            }
        }

#pragma unroll
        for (int r = 0; r < 4; r++) {
            const int ii = ib + r;
            float s = bb2v;
#pragma unroll
            for (int o = 0; o < DPdim; o++)
                s = fmaf(gelu_exact(h[r][o]), sWb2[o], s);
            float abnd = __fdividef(1.0f, 1.0f + __expf(alpha * s));

            float d2z = fmaxf(sRzI[ii] + rzj - 2.0f * dz[r], 0.0f);
            float aint = __expf(-d2z * inv2tau);

            float dp = sPiX[ii] * pjx + sPiY[ii] * pjy + sPiZ[ii] * pjz;
            float d2p = fmaxf(sRpI[ii] + rpj - 2.0f * dp, 0.0f);
            float asp = __expf(-d2p * inv2sig);

            float A = w0 * asp + w1 * aint + w2 * abnd + w3;
            A = __saturatef(A);
            if (I + ii == gj) A = 0.0f;
            sTile[ii][jl] = A;
        }
    }
    __syncthreads();

    // write normal orientation: rows I+r, cols J..J+63
    {
        float* baseN = g_A + ((size_t)b * Ndim + I) * Ndim + J;
#pragma unroll
        for (int q = 0; q < 4; q++) {
            int idx = q * 256 + tid;          // float4 slot 0..1023
            int r = idx >> 4;
            int c = (idx & 15) * 4;
            float4 v = make_float4(sTile[r][c], sTile[r][c + 1],
                                   sTile[r][c + 2], sTile[r][c + 3]);
            *(float4*)(baseN + (size_t)r * Ndim + c) = v;
        }
    }
    // transposed orientation: rows J+r, cols I..I+63
    if (ti != tj) {
        float* baseT = g_A + ((size_t)b * Ndim + J) * Ndim + I;
#pragma unroll
        for (int q = 0; q < 4; q++) {
            int idx = q * 256 + tid;
            int r = idx >> 4;
            int c = (idx & 15) * 4;
            float4 v = make_float4(sTile[c][r], sTile[c + 1][r],
                                   sTile[c + 2][r], sTile[c + 3][r]);
            *(float4*)(baseT + (size_t)r * Ndim + c) = v;
        }
    }
}

// ---------------- kernel 4: per-row top-k + normalize -----------------------
// Threshold via 4-round byte histogram descent (exact, same tie semantics).
__global__ __launch_bounds__(256) void topk_kernel(float* __restrict__ out) {
    __shared__ int sHist[8][256];      // per-warp histograms
    __shared__ int sTot[256];
    __shared__ int sCum[256];          // cumGE per bin
    __shared__ int sSel[2];            // selected bin, new strict-greater G
    __shared__ int sWeq[8];
    __shared__ float sWsum[8];

    const int tid = threadIdx.x;
    const int lane = tid & 31;
    const int warp = tid >> 5;
    const int row = blockIdx.x;

    unsigned vb[8];
    {
        const float4* rowp = (const float4*)(g_A + (size_t)row * Ndim);
        float4 a = rowp[tid * 2 + 0];
        float4 c = rowp[tid * 2 + 1];
        vb[0] = __float_as_uint(a.x); vb[1] = __float_as_uint(a.y);
        vb[2] = __float_as_uint(a.z); vb[3] = __float_as_uint(a.w);
        vb[4] = __float_as_uint(c.x); vb[5] = __float_as_uint(c.y);
        vb[6] = __float_as_uint(c.z); vb[7] = __float_as_uint(c.w);
    }

    unsigned P = 0u;   // prefix (threshold under construction)
    int G = 0;         // strict-greater count from completed rounds

    const int shifts[4]     = {23, 15, 7, 0};
    const int passShifts[4] = {31, 23, 15, 7};

#pragma unroll 1
    for (int rnd = 0; rnd < 4; rnd++) {
        const int shift = shifts[rnd];
        const int pshift = passShifts[rnd];
        const unsigned ppref = P >> pshift;

        // clear per-warp histograms (8*256 ints, 8 per thread)
#pragma unroll
        for (int q = 0; q < 8; q++) ((int*)sHist)[q * 256 + tid] = 0;
        __syncthreads();

#pragma unroll
        for (int r = 0; r < 8; r++) {
            unsigned u = vb[r];
            if ((u >> pshift) == ppref)
                atomicAdd(&sHist[warp][(u >> shift) & 0xFF], 1);
        }
        __syncthreads();

        // totals per bin
        int t = 0;
#pragma unroll
        for (int w = 0; w < 8; w++) t += sHist[w][tid];
        sTot[tid] = t;
        __syncthreads();

        // warp 0: suffix scan -> cumGE[b] = count of passing values with bin >= b
        if (warp == 0) {
            int s = 0;
#pragma unroll
            for (int q = 0; q < 8; q++) s += sTot[lane * 8 + q];
            int S = s;  // inclusive suffix sum across lanes
#pragma unroll
            for (int off = 1; off < 32; off <<= 1) {
                int v = __shfl_down_sync(0xffffffffu, S, off);
                if (lane + off < 32) S += v;
            }
            int running = S - s;  // count in lanes above
#pragma unroll
            for (int q = 7; q >= 0; q--) {
                int bidx = lane * 8 + q;
                running += sTot[bidx];
                sCum[bidx] = running;
            }
        }
        __syncthreads();

        // select largest bin b with G + cumGE[b] >= KSEL (cumGE monotone dec.)
        {
            bool c0 = (G + sCum[tid] >= KSEL);
            bool c1 = (tid == 255) ? false : (G + sCum[tid + 1] >= KSEL);
            if (c0 && !c1) {
                sSel[0] = tid;
                sSel[1] = G + sCum[tid] - sTot[tid];  // strict-greater after this round
            }
        }
        __syncthreads();
        P |= ((unsigned)sSel[0]) << shift;
        G = sSel[1];
        __syncthreads();
    }

    const unsigned T = P;          // exact K-th largest value bits
    const int need = KSEL - G;     // ties at T to keep, in index order

    // exclusive scan of per-thread equal-to-T counts (global index order)
    int eqc = 0;
#pragma unroll
    for (int r = 0; r < 8; r++) eqc += (vb[r] == T);
    int incl = eqc;
#pragma unroll
    for (int off = 1; off < 32; off <<= 1) {
        int t2 = __shfl_up_sync(0xffffffffu, incl, off);
        if (lane >= off) incl += t2;
    }
    if (lane == 31) sWeq[warp] = incl;
    __syncthreads();
    int ebase = incl - eqc;
    for (int w = 0; w < warp; w++) ebase += sWeq[w];

    float ksum = 0.0f;
    {
        int rk = ebase;
#pragma unroll
        for (int r = 0; r < 8; r++) {
            unsigned u = vb[r];
            float v = __uint_as_float(u);
            if (u > T) ksum += v;
            else if (u == T) { if (rk < need) ksum += v; rk++; }
        }
    }
#pragma unroll
    for (int off = 16; off > 0; off >>= 1)
        ksum += __shfl_xor_sync(0xffffffffu, ksum, off);
    if (lane == 0) sWsum[warp] = ksum;
    __syncthreads();
    float tot = 0.0f;
#pragma unroll
    for (int w = 0; w < 8; w++) tot += sWsum[w];
    const float inv = __fdividef(1.0f, fmaxf(tot, EPSV));

    float ov[8];
    {
        int rk = ebase;
#pragma unroll
        for (int r = 0; r < 8; r++) {
            unsigned u = vb[r];
            float v = __uint_as_float(u);
            bool keep = (u > T);
            if (u == T) { keep = (rk < need); rk++; }
            ov[r] = keep ? v * inv : 0.0f;
        }
    }
    float4* orow4 = (float4*)(out + (size_t)row * Ndim);
    orow4[tid * 2 + 0] = make_float4(ov[0], ov[1], ov[2], ov[3]);
    orow4[tid * 2 + 1] = make_float4(ov[4], ov[5], ov[6], ov[7]);
}

extern "C" void kernel_launch(void* const* d_in, const int* in_sizes, int n_in,
                              void* d_out, int out_size) {
    const float* features     = (const float*)d_in[0];
    const float* positions    = (const float*)d_in[1];
    const float* Wi1          = (const float*)d_in[2];
    const float* bi1          = (const float*)d_in[3];
    const float* Wi2          = (const float*)d_in[4];
    const float* bi2          = (const float*)d_in[5];
    const float* Wb1          = (const float*)d_in[6];
    const float* bb1          = (const float*)d_in[7];
    const float* Wb2          = (const float*)d_in[8];
    const float* bb2          = (const float*)d_in[9];
    const float* log_sigma    = (const float*)d_in[10];
    const float* log_tau      = (const float*)d_in[11];
    const float* log_alpha    = (const float*)d_in[12];
    // d_in[13] = log_gamma (unused: EMA buffer empty -> stability == 1)
    const float* prior_logits = (const float*)d_in[14];
    float* out = (float*)d_out;

    prep_kernel<<<(Ndim + 255) / 256, 256>>>(positions);
    z_kernel<<<(Bdim * Ndim * 32) / 256, 256>>>(features, Wi1, bi1, Wi2, bi2);
    tile_kernel<<<Bdim * NTRI, 256>>>(positions, Wb1, bb1, Wb2, bb2,
                                      log_sigma, log_tau, log_alpha, prior_logits);
    topk_kernel<<<Bdim * Ndim, 256>>>(out);
}